// round 1
// baseline (speedup 1.0000x reference)
#include <cuda_runtime.h>
#include <math.h>

#define BB 4
#define NN 4096
#define DD 8
#define K_INST 64
#define TILE 128
#define TMAX (NN / TILE)   /* 32 */
#define T1 512             /* threads, kernel 1 */

// ---------------- scratch (no allocations allowed) ----------------
__device__ float g_cp_emb[BB][NN][DD];   // compacted CP embeddings
__device__ float g_cp_sq [BB][NN];       // compacted CP squared norms
__device__ int   g_pos   [BB];
__device__ int   g_valid [BB];
__device__ float g_partial[BB];          // bce + attraction
__device__ float g_rep_partial[BB][TMAX][TMAX];

__device__ __forceinline__ float softplus_f(float x) {
    // log(1+e^x) = max(x,0) + log1p(exp(-|x|))
    return fmaxf(x, 0.f) + log1pf(expf(-fabsf(x)));
}

// ================= kernel 1: per-batch stats + CP compaction =================
__global__ void k1_stats(const float* __restrict__ beta,
                         const float* __restrict__ embed,
                         const int*   __restrict__ sid,
                         const int*   __restrict__ iscp)
{
    const int b   = blockIdx.x;
    const int tid = threadIdx.x;
    const int base = b * NN;

    __shared__ int   s_first [K_INST];
    __shared__ int   s_cnt   [K_INST];
    __shared__ float s_segsum[K_INST];
    __shared__ float s_cpe   [K_INST][DD];
    __shared__ int   s_scan  [T1];
    __shared__ float s_w1[16], s_w0[16];
    __shared__ float s_attr;

    // zero this batch's rep-partial slots (kernel2 only writes active tiles)
    {
        float* rp = &g_rep_partial[b][0][0];
        for (int q = tid; q < TMAX * TMAX; q += T1) rp[q] = 0.f;
    }
    if (tid < K_INST) {
        s_first[tid]  = NN;
        s_cnt[tid]    = 0;
        s_segsum[tid] = 0.f;
    }
    __syncthreads();

    // ---- phase A: counts, first CP per segment, BCE partial sums ----
    int   lpos = 0;
    float ls1 = 0.f, ls0 = 0.f;
    for (int i = tid; i < NN; i += T1) {
        int   s  = sid [base + i];
        int   c  = iscp[base + i];
        float bt = beta[base + i];
        atomicAdd(&s_cnt[s], 1);
        if (c == 1) {
            lpos++;
            atomicMin(&s_first[s], i);
            ls1 += softplus_f(-bt);
        } else {
            ls0 += softplus_f(bt);
        }
    }
    s_scan[tid] = lpos;
    __syncthreads();
    // inclusive Hillis-Steele scan over 512
    for (int off = 1; off < T1; off <<= 1) {
        int v = (tid >= off) ? s_scan[tid - off] : 0;
        __syncthreads();
        s_scan[tid] += v;
        __syncthreads();
    }
    const int pos_total = s_scan[T1 - 1];

    // ---- compaction pass (deterministic per-thread offsets) ----
    {
        int w = s_scan[tid] - lpos;
        for (int i = tid; i < NN; i += T1) {
            if (iscp[base + i] == 1) {
                const float* e = &embed[(size_t)(base + i) * DD];
                float sq = 0.f;
                #pragma unroll
                for (int d = 0; d < DD; d++) {
                    float v = e[d];
                    g_cp_emb[b][w][d] = v;
                    sq += v * v;
                }
                g_cp_sq[b][w] = sq;
                w++;
            }
        }
    }

    // reduce ls1/ls0 (warp shuffle + smem, fixed order)
    {
        unsigned m = 0xffffffffu;
        float a = ls1, c = ls0;
        #pragma unroll
        for (int off = 16; off; off >>= 1) {
            a += __shfl_down_sync(m, a, off);
            c += __shfl_down_sync(m, c, off);
        }
        if ((tid & 31) == 0) { s_w1[tid >> 5] = a; s_w0[tid >> 5] = c; }
    }
    __syncthreads();

    // load CP-anchor embeddings into smem
    if (tid < K_INST) {
        int f = s_first[tid];
        if (f < NN) {
            const float* e = &embed[(size_t)(base + f) * DD];
            #pragma unroll
            for (int d = 0; d < DD; d++) s_cpe[tid][d] = e[d];
        }
    }
    __syncthreads();

    // ---- phase B: attraction segment sums ----
    for (int i = tid; i < NN; i += T1) {
        int s = sid[base + i];
        if (s_first[s] < NN) {
            const float* e = &embed[(size_t)(base + i) * DD];
            float d2 = 0.f;
            #pragma unroll
            for (int d = 0; d < DD; d++) {
                float df = e[d] - s_cpe[s][d];
                d2 += df * df;
            }
            atomicAdd(&s_segsum[s], d2);
        }
    }
    __syncthreads();

    // ---- phase C: finalize per-batch scalar parts ----
    if (tid == 0) {
        float attr = 0.f;
        for (int k = 0; k < K_INST; k++)
            if (s_first[k] < NN && s_cnt[k] > 0)
                attr += s_segsum[k] / fmaxf((float)s_cnt[k], 1.f);
        s_attr = attr;
    }
    __syncthreads();
    if (tid == 0) {
        float S1 = 0.f, S0 = 0.f;
        for (int w = 0; w < T1 / 32; w++) { S1 += s_w1[w]; S0 += s_w0[w]; }
        float pos = (float)pos_total;
        float neg = (float)NN - pos;
        int valid = (pos >= 1.f) && (neg >= 1.f);
        float pw  = neg / (pos + 1e-6f);
        float bce = (pw * S1 + S0) / (float)NN;
        g_partial[b] = bce + s_attr;
        g_pos[b]     = pos_total;
        g_valid[b]   = valid;
    }
}

// ================= kernel 2: tiled symmetric repulsion =================
__global__ void __launch_bounds__(TILE) k2_rep()
{
    const int ti = blockIdx.x;
    const int tj = blockIdx.y;
    const int b  = blockIdx.z;
    if (tj < ti) return;
    const int P  = g_pos[b];
    const int i0 = ti * TILE;
    const int j0 = tj * TILE;
    if (i0 >= P || j0 >= P) return;

    __shared__ float sE[TILE][DD];
    __shared__ float sSq[TILE];
    __shared__ float sred[TILE];

    const int t  = threadIdx.x;
    const int jn = min(TILE, P - j0);

    // load j-tile (vectorized)
    for (int q = t; q < jn * 2; q += TILE) {
        int row = q >> 1, part = (q & 1) * 4;
        *(float4*)&sE[row][part] = *(const float4*)&g_cp_emb[b][j0 + row][part];
    }
    for (int q = t; q < jn; q += TILE) sSq[q] = g_cp_sq[b][j0 + q];
    __syncthreads();

    const int  gi = i0 + t;
    const bool iv = gi < P;
    float e0=0,e1=0,e2=0,e3=0,e4=0,e5=0,e6=0,e7=0,sqi=0;
    if (iv) {
        float4 a = *(const float4*)&g_cp_emb[b][gi][0];
        float4 c = *(const float4*)&g_cp_emb[b][gi][4];
        e0=a.x; e1=a.y; e2=a.z; e3=a.w;
        e4=c.x; e5=c.y; e6=c.z; e7=c.w;
        sqi = g_cp_sq[b][gi];
    }

    float acc = 0.f;
    #pragma unroll 4
    for (int jj = 0; jj < jn; jj++) {
        float4 a = *(const float4*)&sE[jj][0];   // broadcast (all lanes same addr)
        float4 c = *(const float4*)&sE[jj][4];
        float dot = e0*a.x + e1*a.y + e2*a.z + e3*a.w
                  + e4*c.x + e5*c.y + e6*c.z + e7*c.w;
        float d2 = fmaxf(fmaf(-2.f, dot, sqi + sSq[jj]), 0.f);
        float ex = __expf(-d2);
        acc += (iv && (j0 + jj) > gi) ? ex : 0.f;   // strict upper triangle
    }

    // deterministic block reduce
    sred[t] = acc;
    __syncthreads();
    #pragma unroll
    for (int off = TILE / 2; off > 0; off >>= 1) {
        if (t < off) sred[t] += sred[t + off];
        __syncthreads();
    }
    if (t == 0) g_rep_partial[b][ti][tj] = sred[0];
}

// ================= kernel 3: finalize =================
__global__ void k3_final(float* __restrict__ out)
{
    const int t = threadIdx.x;
    const int w = t >> 5, lane = t & 31;
    __shared__ float s_tot[BB], s_val[BB];

    if (w < BB) {
        const float* rp = &g_rep_partial[w][0][0];
        float s = 0.f;
        for (int q = lane; q < TMAX * TMAX; q += 32) s += rp[q];
        #pragma unroll
        for (int off = 16; off; off >>= 1)
            s += __shfl_down_sync(0xffffffffu, s, off);
        if (lane == 0) {
            float pos = (float)g_pos[w];
            float rep_sum = pos + 2.f * s;          // diagonal = pos exactly
            float rep = (pos > 1.f) ? rep_sum / fmaxf(pos * pos, 1.f) : 0.f;
            float tot = g_partial[w] + rep;
            int v = g_valid[w];
            s_tot[w] = v ? tot : 0.f;
            s_val[w] = v ? 1.f  : 0.f;
        }
    }
    __syncthreads();
    if (t == 0) {
        float ts = 0.f, cnt = 0.f;
        for (int b = 0; b < BB; b++) { ts += s_tot[b]; cnt += s_val[b]; }
        out[0] = (cnt > 0.f) ? ts / fmaxf(cnt, 1.f) : 0.f;
    }
}

// ================= launch =================
extern "C" void kernel_launch(void* const* d_in, const int* in_sizes, int n_in,
                              void* d_out, int out_size)
{
    const float* beta  = (const float*)d_in[0];
    const float* embed = (const float*)d_in[1];
    const int*   sid   = (const int*)  d_in[2];
    const int*   iscp  = (const int*)  d_in[3];
    float* out = (float*)d_out;

    k1_stats<<<BB, T1>>>(beta, embed, sid, iscp);
    dim3 g2(TMAX, TMAX, BB);
    k2_rep<<<g2, TILE>>>();
    k3_final<<<1, 128>>>(out);
}

// round 2
// speedup vs baseline: 1.9640x; 1.9640x over previous
#include <cuda_runtime.h>
#include <math.h>

#define BB 4
#define NN 4096
#define DD 8
#define KK 64              /* instance ids */
#define CC 16              /* chunks per batch */
#define CHUNK 256          /* elements per chunk == threads */
#define TILE 128
#define TMAX (NN / TILE)   /* 32 */

#define LOG2E      1.4426950408889634f
#define TWO_LOG2E  2.8853900817779268f

// ---------------- scratch (no allocations allowed) ----------------
__device__ float g_cp_emb[BB][NN][DD];   // compacted CP embeddings
__device__ float g_cp_sq2[BB][NN];       // compacted |e|^2 * log2(e)
__device__ int   g_pos   [BB];           // ticket counter -> pos; reset by k_final
__device__ int   g_cnt   [BB][CC][KK];   // per-chunk per-segment counts
__device__ int   g_first [BB][CC][KK];   // per-chunk per-segment first-CP index
__device__ float g_bce1  [BB][CC];
__device__ float g_bce0  [BB][CC];
__device__ float g_segsum[BB][CC][KK];
__device__ float g_rep   [BB][TMAX][TMAX];

__device__ __forceinline__ float softplus_f(float x) {
    return fmaxf(x, 0.f) + log1pf(expf(-fabsf(x)));
}
__device__ __forceinline__ float ex2f(float x) {
    float r; asm("ex2.approx.ftz.f32 %0, %1;" : "=f"(r) : "f"(x)); return r;
}

// ============ kernel 1: counts, first-CP, BCE partials, CP compaction ============
__global__ void __launch_bounds__(CHUNK) k_pass1(const float* __restrict__ beta,
                                                 const float* __restrict__ embed,
                                                 const int*   __restrict__ sid,
                                                 const int*   __restrict__ iscp)
{
    const int c   = blockIdx.x;
    const int b   = blockIdx.y;
    const int tid = threadIdx.x;
    const int i   = c * CHUNK + tid;
    const int g   = b * NN + i;

    __shared__ int   s_cnt[KK];
    __shared__ int   s_first[KK];
    __shared__ float s_w1[CHUNK / 32];
    __shared__ float s_w0[CHUNK / 32];

    if (tid < KK) { s_cnt[tid] = 0; s_first[tid] = NN; }
    __syncthreads();

    const int   s  = sid[g];
    const int   cp = iscp[g];
    const float bt = beta[g];

    atomicAdd(&s_cnt[s], 1);
    float l1 = 0.f, l0 = 0.f;
    if (cp == 1) { atomicMin(&s_first[s], i); l1 = softplus_f(-bt); }
    else         { l0 = softplus_f(bt); }

    // ---- warp-aggregated compaction ticket (integer -> exact) ----
    const int      lane = tid & 31;
    const unsigned bal  = __ballot_sync(0xffffffffu, cp == 1);
    if (bal) {
        const int nw = __popc(bal);
        const int leader = __ffs(bal) - 1;
        int base = 0;
        if (lane == leader) base = atomicAdd(&g_pos[b], nw);
        base = __shfl_sync(0xffffffffu, base, leader);
        if (cp == 1) {
            const int w = base + __popc(bal & ((1u << lane) - 1u));
            const float4* e = (const float4*)&embed[(size_t)g * DD];
            float4 a = e[0], d = e[1];
            float sq = a.x*a.x + a.y*a.y + a.z*a.z + a.w*a.w
                     + d.x*d.x + d.y*d.y + d.z*d.z + d.w*d.w;
            *(float4*)&g_cp_emb[b][w][0] = a;
            *(float4*)&g_cp_emb[b][w][4] = d;
            g_cp_sq2[b][w] = sq * LOG2E;
        }
    }

    // ---- BCE partial reduce (fixed order) ----
    #pragma unroll
    for (int off = 16; off; off >>= 1) {
        l1 += __shfl_down_sync(0xffffffffu, l1, off);
        l0 += __shfl_down_sync(0xffffffffu, l0, off);
    }
    if (lane == 0) { s_w1[tid >> 5] = l1; s_w0[tid >> 5] = l0; }
    __syncthreads();

    if (tid < KK) { g_cnt[b][c][tid] = s_cnt[tid]; g_first[b][c][tid] = s_first[tid]; }
    if (tid == 0) {
        float S1 = 0.f, S0 = 0.f;
        #pragma unroll
        for (int w = 0; w < CHUNK / 32; w++) { S1 += s_w1[w]; S0 += s_w0[w]; }
        g_bce1[b][c] = S1;
        g_bce0[b][c] = S0;
    }
}

// ============ kernel 2: attraction segment sums ============
__global__ void __launch_bounds__(CHUNK) k_pass2(const float* __restrict__ embed,
                                                 const int*   __restrict__ sid)
{
    const int c   = blockIdx.x;
    const int b   = blockIdx.y;
    const int tid = threadIdx.x;

    __shared__ int   s_first[KK];
    __shared__ float s_cpe[KK][DD];
    __shared__ float s_seg[KK];

    if (tid < KK) {
        int f = NN;
        #pragma unroll
        for (int cc = 0; cc < CC; cc++) f = min(f, g_first[b][cc][tid]);
        s_first[tid] = f;
        s_seg[tid]   = 0.f;
        if (f < NN) {
            const float4* e = (const float4*)&embed[((size_t)b * NN + f) * DD];
            *(float4*)&s_cpe[tid][0] = e[0];
            *(float4*)&s_cpe[tid][4] = e[1];
        }
    }
    __syncthreads();

    const int i = c * CHUNK + tid;
    const int g = b * NN + i;
    const int s = sid[g];
    if (s_first[s] < NN) {
        const float4* e = (const float4*)&embed[(size_t)g * DD];
        float4 a = e[0], d = e[1];
        float x0 = a.x - s_cpe[s][0], x1 = a.y - s_cpe[s][1];
        float x2 = a.z - s_cpe[s][2], x3 = a.w - s_cpe[s][3];
        float x4 = d.x - s_cpe[s][4], x5 = d.y - s_cpe[s][5];
        float x6 = d.z - s_cpe[s][6], x7 = d.w - s_cpe[s][7];
        float d2 = x0*x0 + x1*x1 + x2*x2 + x3*x3 + x4*x4 + x5*x5 + x6*x6 + x7*x7;
        atomicAdd(&s_seg[s], d2);
    }
    __syncthreads();
    if (tid < KK) g_segsum[b][c][tid] = s_seg[tid];
}

// ============ kernel 3: tiled symmetric repulsion ============
__global__ void __launch_bounds__(TILE) k_rep()
{
    const int ti = blockIdx.x;
    const int tj = blockIdx.y;
    const int b  = blockIdx.z;
    if (tj < ti) return;
    const int P  = g_pos[b];
    const int i0 = ti * TILE;
    const int j0 = tj * TILE;
    if (i0 >= P || j0 >= P) return;

    __shared__ float sE[TILE][DD];
    __shared__ float sQ[TILE];
    __shared__ float sred[TILE];

    const int t  = threadIdx.x;
    const int jn = min(TILE, P - j0);

    for (int q = t; q < jn * 2; q += TILE) {
        int r = q >> 1, p = (q & 1) * 4;
        *(float4*)&sE[r][p] = *(const float4*)&g_cp_emb[b][j0 + r][p];
    }
    if (t < jn) sQ[t] = g_cp_sq2[b][j0 + t];
    __syncthreads();

    const int  gi = i0 + t;
    const bool iv = gi < P;
    float e0=0,e1=0,e2=0,e3=0,e4=0,e5=0,e6=0,e7=0, nq=0.f;
    if (iv) {
        float4 a = *(const float4*)&g_cp_emb[b][gi][0];
        float4 d = *(const float4*)&g_cp_emb[b][gi][4];
        e0=a.x; e1=a.y; e2=a.z; e3=a.w;
        e4=d.x; e5=d.y; e6=d.z; e7=d.w;
        nq = -g_cp_sq2[b][gi];
    }

    float acc = 0.f;
    if (ti != tj && jn == TILE) {
        // clean full off-diagonal tile: every (i,j) with i<P valid, i<j guaranteed
        if (iv) {
            #pragma unroll 4
            for (int jj = 0; jj < TILE; jj++) {
                float4 a = *(const float4*)&sE[jj][0];
                float4 d = *(const float4*)&sE[jj][4];
                float dot = e0*a.x + e1*a.y + e2*a.z + e3*a.w
                          + e4*d.x + e5*d.y + e6*d.z + e7*d.w;
                float arg = fminf(fmaf(dot, TWO_LOG2E, nq - sQ[jj]), 0.f);
                acc += ex2f(arg);
            }
        }
    } else {
        #pragma unroll 4
        for (int jj = 0; jj < jn; jj++) {
            float4 a = *(const float4*)&sE[jj][0];
            float4 d = *(const float4*)&sE[jj][4];
            float dot = e0*a.x + e1*a.y + e2*a.z + e3*a.w
                      + e4*d.x + e5*d.y + e6*d.z + e7*d.w;
            float arg = fminf(fmaf(dot, TWO_LOG2E, nq - sQ[jj]), 0.f);
            float ex  = ex2f(arg);
            acc += (iv && (j0 + jj) > gi) ? ex : 0.f;   // strict upper triangle
        }
    }

    sred[t] = acc;
    __syncthreads();
    #pragma unroll
    for (int off = TILE / 2; off > 0; off >>= 1) {
        if (t < off) sred[t] += sred[t + off];
        __syncthreads();
    }
    if (t == 0) g_rep[b][ti][tj] = sred[0];
}

// ============ kernel 4: finalize (and reset ticket counters) ============
__global__ void __launch_bounds__(256) k_final(float* __restrict__ out)
{
    const int t    = threadIdx.x;
    const int b    = t >> 6;         // 4 batches x 64 lanes
    const int k    = t & 63;
    const int lane = t & 31;
    const int wrp  = t >> 5;         // warp id 0..7, b = wrp>>1

    __shared__ float p_attr[8], p_rep[8], p_b1[8], p_b0[8];
    __shared__ float s_tot[BB], s_val[BB];

    const int P = g_pos[b];

    // attraction: per-segment totals
    int   cntk = 0, fk = NN;
    float segk = 0.f;
    #pragma unroll
    for (int c = 0; c < CC; c++) {
        cntk += g_cnt[b][c][k];
        fk    = min(fk, g_first[b][c][k]);
        segk += g_segsum[b][c][k];
    }
    float attr = (fk < NN && cntk > 0) ? segk / fmaxf((float)cntk, 1.f) : 0.f;

    // bce partials: chunks 0..CC-1 held by k < CC
    float b1 = (k < CC) ? g_bce1[b][k] : 0.f;
    float b0 = (k < CC) ? g_bce0[b][k] : 0.f;

    // repulsion partials over active tiles
    float rep = 0.f;
    #pragma unroll
    for (int q = 0; q < (TMAX * TMAX) / 64; q++) {
        int idx = k + q * 64;
        int ti = idx >> 5, tj = idx & 31;
        if (tj >= ti && ti * TILE < P && tj * TILE < P)
            rep += g_rep[b][ti][tj];
    }

    #pragma unroll
    for (int off = 16; off; off >>= 1) {
        attr += __shfl_down_sync(0xffffffffu, attr, off);
        rep  += __shfl_down_sync(0xffffffffu, rep,  off);
        b1   += __shfl_down_sync(0xffffffffu, b1,   off);
        b0   += __shfl_down_sync(0xffffffffu, b0,   off);
    }
    if (lane == 0) { p_attr[wrp] = attr; p_rep[wrp] = rep; p_b1[wrp] = b1; p_b0[wrp] = b0; }
    __syncthreads();

    if (k == 0) {
        float A  = p_attr[2*b] + p_attr[2*b + 1];
        float R  = p_rep [2*b] + p_rep [2*b + 1];
        float S1 = p_b1  [2*b] + p_b1  [2*b + 1];
        float S0 = p_b0  [2*b] + p_b0  [2*b + 1];
        float pos = (float)P;
        float neg = (float)NN - pos;
        int   valid = (pos >= 1.f) && (neg >= 1.f);
        float pw  = neg / (pos + 1e-6f);
        float bce = (pw * S1 + S0) / (float)NN;
        float rep_sum = pos + 2.f * R;            // diagonal contributes exactly pos
        float repl = (pos > 1.f) ? rep_sum / fmaxf(pos * pos, 1.f) : 0.f;
        float tot = bce + A + repl;
        s_tot[b] = valid ? tot : 0.f;
        s_val[b] = valid ? 1.f : 0.f;
    }
    __syncthreads();
    if (t == 0) {
        float ts = 0.f, cnt = 0.f;
        #pragma unroll
        for (int bb = 0; bb < BB; bb++) { ts += s_tot[bb]; cnt += s_val[bb]; }
        out[0] = (cnt > 0.f) ? ts / fmaxf(cnt, 1.f) : 0.f;
    }
    __syncthreads();
    if (t < BB) g_pos[t] = 0;   // ticket reset for the next replay
}

// ================= launch =================
extern "C" void kernel_launch(void* const* d_in, const int* in_sizes, int n_in,
                              void* d_out, int out_size)
{
    const float* beta  = (const float*)d_in[0];
    const float* embed = (const float*)d_in[1];
    const int*   sid   = (const int*)  d_in[2];
    const int*   iscp  = (const int*)  d_in[3];
    float* out = (float*)d_out;

    dim3 g1(CC, BB);
    k_pass1<<<g1, CHUNK>>>(beta, embed, sid, iscp);
    k_pass2<<<g1, CHUNK>>>(embed, sid);
    dim3 g2(TMAX, TMAX, BB);
    k_rep<<<g2, TILE>>>();
    k_final<<<1, 256>>>(out);
}